// round 2
// baseline (speedup 1.0000x reference)
#include <cuda_runtime.h>
#include <math.h>

// ---------------------------------------------------------------------------
// SiamFC head, round 2: packed f32x2 FMA correlation.
//   x' = gelu(x + dw3x3(x,wx) + bx)   (64,64,96,96)
//   z' = gelu(z + dw3x3(z,wz) + bz)   (64,64,16,16)
//   out[b,i,j] = 0.001 * sum_{c,p,q} z'[b,c,p,q] * x'[b,c,i+p-8, j+q-8]
// XP padded to [120][120] per plane (rows/cols shifted by +8), pads stay zero.
// Correlation inner loop pairs q as (q, q+1) into one fma.rn.f32x2 with a
// packed accumulator; lo+hi summed in the epilogue.
// ---------------------------------------------------------------------------

typedef unsigned long long u64;

__device__ float XP[64 * 64 * 120 * 120];  // padded x'
__device__ float ZPd[64 * 64 * 256];       // z'

__device__ __forceinline__ float gelu_exact(float v) {
    return 0.5f * v * (1.0f + erff(v * 0.70710678118654752f));
}

__device__ __forceinline__ u64 pk(float x, float y) {
    u64 r; asm("mov.b64 %0, {%1,%2};" : "=l"(r) : "f"(x), "f"(y)); return r;
}
__device__ __forceinline__ void upk(u64 v, float& x, float& y) {
    asm("mov.b64 {%0,%1}, %2;" : "=f"(x), "=f"(y) : "l"(v));
}
__device__ __forceinline__ u64 ffma2(u64 a, u64 b, u64 c) {
    u64 d; asm("fma.rn.f32x2 %0, %1, %2, %3;" : "=l"(d) : "l"(a), "l"(b), "l"(c));
    return d;
}

// ---- Kernel A: preprocess x -> XP, full-line float4 stores ------------------
__global__ __launch_bounds__(256) void prep_x(const float* __restrict__ x,
                                              const float* __restrict__ wx,
                                              const float* __restrict__ bx) {
    int bc = blockIdx.x;        // b*64 + c
    int c  = bc & 63;
    __shared__ float sp[98 * 100];  // zero-padded 96x96 plane (halo 1)

    for (int i = threadIdx.x; i < 98 * 100; i += 256) sp[i] = 0.0f;
    __syncthreads();

    const float* xp = x + (size_t)bc * 9216;
    for (int i = threadIdx.x; i < 9216; i += 256) {
        int r = i / 96, cl = i - r * 96;
        sp[(r + 1) * 100 + (cl + 1)] = xp[i];
    }
    __syncthreads();

    float w[9];
#pragma unroll
    for (int k = 0; k < 9; ++k) w[k] = __ldg(wx + c * 9 + k);
    float bias = __ldg(bx + c);

    // Write rows 8..103 (96 rows) of the 120-wide padded plane, all 120 cols,
    // as float4 (30 per row). Pad cols get explicit zeros -> full cache lines.
    float* dst = XP + (size_t)bc * (120 * 120);
    for (int g = threadIdx.x; g < 96 * 30; g += 256) {
        int r = g / 30, q4 = g - r * 30;
        float4 o;
        float* ov = &o.x;
#pragma unroll
        for (int u = 0; u < 4; ++u) {
            int pc = 4 * q4 + u;     // padded col 0..119
            int xc = pc - 8;         // x col
            float val = 0.0f;
            if (xc >= 0 && xc < 96) {
                float conv = bias;
#pragma unroll
                for (int di = 0; di < 3; ++di)
#pragma unroll
                    for (int dj = 0; dj < 3; ++dj)
                        conv = fmaf(w[di * 3 + dj], sp[(r + di) * 100 + (xc + dj)], conv);
                float v = sp[(r + 1) * 100 + (xc + 1)];
                val = gelu_exact(v + conv);
            }
            ov[u] = val;
        }
        reinterpret_cast<float4*>(dst + (r + 8) * 120)[q4] = o;
    }
}

// ---- Kernel B: preprocess z -> ZPd ------------------------------------------
__global__ __launch_bounds__(256) void prep_z(const float* __restrict__ z,
                                              const float* __restrict__ wz,
                                              const float* __restrict__ bz) {
    int bc = blockIdx.x;
    int c  = bc & 63;
    __shared__ float sp[18 * 18];

    for (int i = threadIdx.x; i < 18 * 18; i += 256) sp[i] = 0.0f;
    __syncthreads();

    int t = threadIdx.x;
    int p = t >> 4, q = t & 15;
    sp[(p + 1) * 18 + (q + 1)] = z[(size_t)bc * 256 + t];
    __syncthreads();

    float conv = __ldg(bz + c);
#pragma unroll
    for (int di = 0; di < 3; ++di)
#pragma unroll
        for (int dj = 0; dj < 3; ++dj)
            conv = fmaf(__ldg(wz + c * 9 + di * 3 + dj), sp[(p + di) * 18 + (q + dj)], conv);
    float v = sp[(p + 1) * 18 + (q + 1)];
    ZPd[(size_t)bc * 256 + t] = gelu_exact(v + conv);
}

// ---- Kernel C: correlation, f32x2 packed ------------------------------------
// Grid (13, 64). 128 threads = 4 warps; warp w owns output rows i0+2w, i0+2w+1.
// Lane L<=24 owns cols 4L..4L+3. Window row k serves row0 with z-row p=k and
// row1 with z-row p=k-1 (same window data).
__global__ __launch_bounds__(128) void corr(float* __restrict__ out) {
    int ib = blockIdx.x, b = blockIdx.y;
    int i0 = ib * 8;
    int tid  = threadIdx.x;
    int w    = tid >> 5;
    int lane = tid & 31;
    int jb = (lane <= 24) ? (lane * 4) : 0;

    __shared__ __align__(16) float zc[256];
    __shared__ __align__(16) float xw[23 * 120];

    u64 acc0[4] = {0ull, 0ull, 0ull, 0ull};
    u64 acc1[4] = {0ull, 0ull, 0ull, 0ull};

    const float4* zsrc = reinterpret_cast<const float4*>(ZPd + (size_t)b * 64 * 256);

    for (int c = 0; c < 64; ++c) {
        __syncthreads();
        if (tid < 64)
            reinterpret_cast<float4*>(zc)[tid] = zsrc[c * 64 + tid];
        const float4* src =
            reinterpret_cast<const float4*>(XP + (size_t)((b * 64 + c) * 120 + i0) * 120);
        for (int k = tid; k < 690; k += 128)  // 23*120/4 float4
            reinterpret_cast<float4*>(xw)[k] = src[k];
        __syncthreads();

#pragma unroll 1
        for (int k = 0; k < 17; ++k) {
            // window pairs: e[v] = (win[2v], win[2v+1]), o[v] = (win[2v+1], win[2v+2])
            const u64* wp = reinterpret_cast<const u64*>(xw + (2 * w + k) * 120 + jb);
            u64 e[10];
            float lo[10], hi[10];
#pragma unroll
            for (int v = 0; v < 10; ++v) { e[v] = wp[v]; upk(e[v], lo[v], hi[v]); }
            u64 o[9];
#pragma unroll
            for (int v = 0; v < 9; ++v) o[v] = pk(hi[v], lo[v + 1]);

            if (k < 16) {  // output row0, z-row p = k
                const u64* zp = reinterpret_cast<const u64*>(zc + k * 16);
#pragma unroll
                for (int q2 = 0; q2 < 8; ++q2) {
                    u64 z2 = zp[q2];
                    acc0[0] = ffma2(z2, e[q2],     acc0[0]);
                    acc0[1] = ffma2(z2, o[q2],     acc0[1]);
                    acc0[2] = ffma2(z2, e[q2 + 1], acc0[2]);
                    acc0[3] = ffma2(z2, o[q2 + 1], acc0[3]);
                }
            }
            if (k >= 1) {  // output row1, z-row p = k-1
                const u64* zp = reinterpret_cast<const u64*>(zc + (k - 1) * 16);
#pragma unroll
                for (int q2 = 0; q2 < 8; ++q2) {
                    u64 z2 = zp[q2];
                    acc1[0] = ffma2(z2, e[q2],     acc1[0]);
                    acc1[1] = ffma2(z2, o[q2],     acc1[1]);
                    acc1[2] = ffma2(z2, e[q2 + 1], acc1[2]);
                    acc1[3] = ffma2(z2, o[q2 + 1], acc1[3]);
                }
            }
        }
    }

    if (lane <= 24) {
        int irow = i0 + 2 * w;
#pragma unroll
        for (int cc = 0; cc < 4; ++cc) {
            int j = jb + cc;
            if (j < 97) {
                float a, bx2, r0, r1;
                upk(acc0[cc], a, bx2); r0 = a + bx2;
                upk(acc1[cc], a, bx2); r1 = a + bx2;
                if (irow < 97)
                    out[(size_t)b * 9409 + irow * 97 + j] = r0 * 0.001f;
                if (irow + 1 < 97)
                    out[(size_t)b * 9409 + (irow + 1) * 97 + j] = r1 * 0.001f;
            }
        }
    }
}

// ---- launch ------------------------------------------------------------------
extern "C" void kernel_launch(void* const* d_in, const int* in_sizes, int n_in,
                              void* d_out, int out_size) {
    const float* z  = (const float*)d_in[0];
    const float* x  = (const float*)d_in[1];
    const float* wz = (const float*)d_in[2];
    const float* bz = (const float*)d_in[3];
    const float* wx = (const float*)d_in[4];
    const float* bx = (const float*)d_in[5];
    float* out = (float*)d_out;

    prep_x<<<4096, 256>>>(x, wx, bx);
    prep_z<<<4096, 256>>>(z, wz, bz);
    corr<<<dim3(13, 64), 128>>>(out);
}

// round 3
// speedup vs baseline: 2.7725x; 2.7725x over previous
#include <cuda_runtime.h>
#include <cuda_fp16.h>
#include <math.h>

// ---------------------------------------------------------------------------
// SiamFC head, round 3: HMMA fp16 factorized correlation.
//   H[b,r,j,p] = sum_{c,q} x'[b,c,r-8,j+q-8] * z'[b,c,p,q]   (GEMM, tensor cores)
//   out[b,i,j] = 0.001 * sum_p H[b,i+p,j,p]                  (shift-add epilogue)
// x' stored fp16 zero-padded [b][c][112][112]; z' fp16 [b][c][16][16].
// ---------------------------------------------------------------------------

__device__ __align__(16) unsigned XG[64 * 64 * 112 * 56];  // x' fp16 (half2 words), padded 112x112
__device__ __align__(16) unsigned ZHW[64 * 64 * 128];      // z' fp16 [b][c][16][16] as words
__device__ __align__(16) float Hbuf[64 * 112 * 16 * 112];  // H[b][r][p][j]

__device__ __forceinline__ float gelu_exact(float v) {
    return 0.5f * v * (1.0f + erff(v * 0.70710678118654752f));
}

// ---- Kernel A: preprocess x -> XG (fp16, padded, full half2 rows) -----------
__global__ __launch_bounds__(256) void prep_x(const float* __restrict__ x,
                                              const float* __restrict__ wx,
                                              const float* __restrict__ bx) {
    int bc = blockIdx.x;        // b*64 + c
    int c  = bc & 63;
    __shared__ float sp[98 * 100];  // zero-padded 96x96 plane (halo 1)

    for (int i = threadIdx.x; i < 98 * 100; i += 256) sp[i] = 0.0f;
    __syncthreads();

    const float* xp = x + (size_t)bc * 9216;
    for (int i = threadIdx.x; i < 9216; i += 256) {
        int r = i / 96, cl = i - r * 96;
        sp[(r + 1) * 100 + (cl + 1)] = xp[i];
    }
    __syncthreads();

    float w[9];
#pragma unroll
    for (int k = 0; k < 9; ++k) w[k] = __ldg(wx + c * 9 + k);
    float bias = __ldg(bx + c);

    unsigned* dst = XG + (size_t)bc * (112 * 56);
    for (int g = threadIdx.x; g < 112 * 56; g += 256) {
        int r = g / 56, wd = g - r * 56;   // padded row r, half2 word wd
        int xr = r - 8;
        float f0 = 0.0f, f1 = 0.0f;
        if (xr >= 0 && xr < 96) {
#pragma unroll
            for (int u = 0; u < 2; ++u) {
                int xc = 2 * wd + u - 8;
                if (xc >= 0 && xc < 96) {
                    float conv = bias;
#pragma unroll
                    for (int di = 0; di < 3; ++di)
#pragma unroll
                        for (int dj = 0; dj < 3; ++dj)
                            conv = fmaf(w[di * 3 + dj], sp[(xr + di) * 100 + (xc + dj)], conv);
                    float v = sp[(xr + 1) * 100 + (xc + 1)];
                    float g2 = gelu_exact(v + conv);
                    if (u) f1 = g2; else f0 = g2;
                }
            }
        }
        __half2 h = __floats2half2_rn(f0, f1);
        dst[g] = *reinterpret_cast<unsigned*>(&h);
    }
}

// ---- Kernel B: preprocess z -> ZHW (fp16) ------------------------------------
__global__ __launch_bounds__(256) void prep_z(const float* __restrict__ z,
                                              const float* __restrict__ wz,
                                              const float* __restrict__ bz) {
    int bc = blockIdx.x;
    int c  = bc & 63;
    __shared__ float sp[18 * 18];

    for (int i = threadIdx.x; i < 18 * 18; i += 256) sp[i] = 0.0f;
    __syncthreads();

    int t = threadIdx.x;  // (p,q)
    int p = t >> 4, q = t & 15;
    sp[(p + 1) * 18 + (q + 1)] = z[(size_t)bc * 256 + t];
    __syncthreads();

    float conv = __ldg(bz + c);
#pragma unroll
    for (int di = 0; di < 3; ++di)
#pragma unroll
        for (int dj = 0; dj < 3; ++dj)
            conv = fmaf(__ldg(wz + c * 9 + di * 3 + dj), sp[(p + di) * 18 + (q + dj)], conv);
    float v = sp[(p + 1) * 18 + (q + 1)];
    reinterpret_cast<__half*>(ZHW)[(size_t)bc * 256 + t] = __float2half(gelu_exact(v + conv));
}

// ---- Kernel C: correlation GEMM on tensor cores ------------------------------
// One CTA per (b, r). 4 warps; warp w owns j-tiles {w, w+4, w+8, w+12} (<14).
// Per k-step c: A frag = z'[b][c] (m=p16, k=q16), B frag = sliding window of
// XQ row c (k=q16, n=j8). Even + odd-shifted SMEM row copies give aligned LDS.32.
#define XQO_WOFF 4112  // odd-copy word offset (4096 + 16 pad words -> distinct banks)
__global__ __launch_bounds__(128) void corr() {
    int r = blockIdx.x, b = blockIdx.y;
    int tid = threadIdx.x, lane = tid & 31, w = tid >> 5;

    __shared__ unsigned sq[XQO_WOFF + 4096];

    // Stage even copy: sq[c*64 + wd] = XG[b][c][r] words (56 valid, 8 zero pad)
    for (int t = tid; t < 4096; t += 128) {
        int c = t >> 6, wd = t & 63;
        unsigned v = 0;
        if (wd < 56) v = XG[(size_t)(b * 64 + c) * 6272 + r * 56 + wd];
        sq[t] = v;
    }
    __syncthreads();
    // Build odd-shifted copy: word = halves (2t+1, 2t+2)
    for (int t = tid; t < 4096; t += 128) {
        int c = t >> 6, wd = t & 63;
        unsigned lo = sq[(c << 6) + wd] >> 16;
        unsigned hi = (wd < 63) ? (sq[(c << 6) + wd + 1] << 16) : 0u;
        sq[XQO_WOFF + t] = lo | hi;
    }
    __syncthreads();

    // Per-lane B-fragment addressing
    int nj = lane >> 2;            // n within j-tile (0..7)
    int q0 = (lane & 3) << 1;      // 0,2,4,6
    int widx = (nj + q0) >> 1;     // word index within row
    const unsigned* bbase = sq + ((nj & 1) ? XQO_WOFF : 0) + widx + (w << 2);

    // Per-lane A-fragment addressing (z' words): p*8 + (lane&3)
    const unsigned* zb = ZHW + (size_t)b * 64 * 128;
    int aoff = (lane >> 2) * 8 + (lane & 3);

    float acc[4][4];
#pragma unroll
    for (int u = 0; u < 4; ++u)
#pragma unroll
        for (int k = 0; k < 4; ++k) acc[u][k] = 0.0f;

#pragma unroll 1
    for (int c = 0; c < 64; ++c) {
        const unsigned* za = zb + c * 128 + aoff;
        unsigned a0 = __ldg(za);        // (p, q0..q0+1)
        unsigned a1 = __ldg(za + 64);   // (p+8, q0..)
        unsigned a2 = __ldg(za + 4);    // (p, q0+8..)
        unsigned a3 = __ldg(za + 68);   // (p+8, q0+8..)
        const unsigned* bp = bbase + (c << 6);
#pragma unroll
        for (int u = 0; u < 4; ++u) {
            if (w + 4 * u < 14) {
                unsigned b0 = bp[u * 16];
                unsigned b1 = bp[u * 16 + 4];
                asm volatile(
                    "mma.sync.aligned.m16n8k16.row.col.f32.f16.f16.f32 "
                    "{%0,%1,%2,%3}, {%4,%5,%6,%7}, {%8,%9}, {%0,%1,%2,%3};"
                    : "+f"(acc[u][0]), "+f"(acc[u][1]), "+f"(acc[u][2]), "+f"(acc[u][3])
                    : "r"(a0), "r"(a1), "r"(a2), "r"(a3), "r"(b0), "r"(b1));
            }
        }
    }

    // Store H[b][r][p][j]
    int p0 = lane >> 2, jn = (lane & 3) << 1;
    float* Hb = Hbuf + (size_t)(b * 112 + r) * (16 * 112);
#pragma unroll
    for (int u = 0; u < 4; ++u) {
        int jt = w + 4 * u;
        if (jt < 14) {
            int j = jt * 8 + jn;
            *reinterpret_cast<float2*>(Hb + p0 * 112 + j)       = make_float2(acc[u][0], acc[u][1]);
            *reinterpret_cast<float2*>(Hb + (p0 + 8) * 112 + j) = make_float2(acc[u][2], acc[u][3]);
        }
    }
}

// ---- Kernel D: shift-add epilogue --------------------------------------------
__global__ __launch_bounds__(256) void epilogue(float* __restrict__ out) {
    int t = blockIdx.x * 256 + threadIdx.x;
    if (t >= 64 * 97 * 97) return;
    int b = t / 9409, rem = t - b * 9409;
    int i = rem / 97, j = rem - i * 97;
    const float* Hb = Hbuf + (size_t)b * (112 * 16 * 112);
    float s = 0.0f;
#pragma unroll
    for (int p = 0; p < 16; ++p)
        s += Hb[(size_t)((i + p) * 16 + p) * 112 + j];
    out[t] = s * 0.001f;
}

// ---- launch --------------------------------------------------------------------
extern "C" void kernel_launch(void* const* d_in, const int* in_sizes, int n_in,
                              void* d_out, int out_size) {
    const float* z  = (const float*)d_in[0];
    const float* x  = (const float*)d_in[1];
    const float* wz = (const float*)d_in[2];
    const float* bz = (const float*)d_in[3];
    const float* wx = (const float*)d_in[4];
    const float* bx = (const float*)d_in[5];
    float* out = (float*)d_out;

    prep_x<<<4096, 256>>>(x, wx, bx);
    prep_z<<<4096, 256>>>(z, wz, bz);
    corr<<<dim3(112, 64), 128>>>();
    epilogue<<<(64 * 97 * 97 + 255) / 256, 256>>>(out);
}

// round 4
// speedup vs baseline: 3.3073x; 1.1929x over previous
#include <cuda_runtime.h>
#include <cuda_fp16.h>
#include <math.h>

// ---------------------------------------------------------------------------
// SiamFC head, round 4: HMMA fp16 factorized correlation, pipelined.
//   H[b,r,j,p] = sum_{c,q} x'[b,c,r-8,j+q-8] * z'[b,c,p,q]   (tensor cores)
//   out[b,i,j] = 0.001 * sum_p H[b,i+p,j,p]                  (shift-add)
// x' fp16 zero-padded [b][c][112][112]; z' fp16 [b][c][16][16].
// Only r=8..103 and j-tiles 0..12 are computed (rest provably zero / unread).
// ---------------------------------------------------------------------------

__device__ __align__(16) unsigned XG[64 * 64 * 112 * 56];  // x' fp16 half2 words
__device__ __align__(16) unsigned ZHW[64 * 64 * 128];      // z' fp16 words
__device__ __align__(16) float Hbuf[64 * 112 * 16 * 112];  // H[b][r][p][j]

__device__ __forceinline__ float gelu_exact(float v) {
    return 0.5f * v * (1.0f + erff(v * 0.70710678118654752f));
}

// ---- Kernel A: preprocess x -> XG, interior-only uint4 stores ----------------
__global__ __launch_bounds__(256) void prep_x(const float* __restrict__ x,
                                              const float* __restrict__ wx,
                                              const float* __restrict__ bx) {
    int bc = blockIdx.x;        // b*64 + c
    int c  = bc & 63;
    __shared__ float sp[98 * 100];  // zero-padded 96x96 plane (halo 1)

    for (int i = threadIdx.x; i < 98 * 100; i += 256) sp[i] = 0.0f;
    __syncthreads();

    const float* xp = x + (size_t)bc * 9216;
    for (int i = threadIdx.x; i < 9216; i += 256) {
        int r = i / 96, cl = i - r * 96;
        sp[(r + 1) * 100 + (cl + 1)] = xp[i];
    }
    __syncthreads();

    float w[9];
#pragma unroll
    for (int k = 0; k < 9; ++k) w[k] = __ldg(wx + c * 9 + k);
    float bias = __ldg(bx + c);

    // Interior = padded rows 8..103, padded words 4..51 (cols 8..103).
    // 12 uint4 per row, 96 rows. Pads are never written (stay zero from init).
    uint4* dst = reinterpret_cast<uint4*>(XG + (size_t)bc * (112 * 56));
    for (int g = threadIdx.x; g < 96 * 12; g += 256) {
        int r = g / 12, v4 = g - r * 12;
        int xc0 = v4 * 8;
        unsigned ow[4];
#pragma unroll
        for (int t = 0; t < 4; ++t) {
            float f[2];
#pragma unroll
            for (int u = 0; u < 2; ++u) {
                int xc = xc0 + 2 * t + u;
                float conv = bias;
#pragma unroll
                for (int di = 0; di < 3; ++di)
#pragma unroll
                    for (int dj = 0; dj < 3; ++dj)
                        conv = fmaf(w[di * 3 + dj], sp[(r + di) * 100 + (xc + dj)], conv);
                float v = sp[(r + 1) * 100 + (xc + 1)];
                f[u] = gelu_exact(v + conv);
            }
            __half2 h = __floats2half2_rn(f[0], f[1]);
            ow[t] = *reinterpret_cast<unsigned*>(&h);
        }
        dst[(r + 8) * 14 + 1 + v4] = make_uint4(ow[0], ow[1], ow[2], ow[3]);
    }
}

// ---- Kernel B: preprocess z -> ZHW (fp16) ------------------------------------
__global__ __launch_bounds__(256) void prep_z(const float* __restrict__ z,
                                              const float* __restrict__ wz,
                                              const float* __restrict__ bz) {
    int bc = blockIdx.x;
    int c  = bc & 63;
    __shared__ float sp[18 * 18];

    for (int i = threadIdx.x; i < 18 * 18; i += 256) sp[i] = 0.0f;
    __syncthreads();

    int t = threadIdx.x;
    int p = t >> 4, q = t & 15;
    sp[(p + 1) * 18 + (q + 1)] = z[(size_t)bc * 256 + t];
    __syncthreads();

    float conv = __ldg(bz + c);
#pragma unroll
    for (int di = 0; di < 3; ++di)
#pragma unroll
        for (int dj = 0; dj < 3; ++dj)
            conv = fmaf(__ldg(wz + c * 9 + di * 3 + dj), sp[(p + di) * 18 + (q + dj)], conv);
    float v = sp[(p + 1) * 18 + (q + 1)];
    reinterpret_cast<__half*>(ZHW)[(size_t)bc * 256 + t] = __float2half(gelu_exact(v + conv));
}

// ---- Kernel C: correlation GEMM, A-fragment register pipeline ----------------
// One CTA per (b, r=8..103). 4 warps; warp w owns j-tiles {w, w+4, w+8, w+12}<13.
#define XQO_WOFF 4112  // odd-copy word offset
__global__ __launch_bounds__(128) void corr() {
    int r = blockIdx.x + 8, b = blockIdx.y;
    int tid = threadIdx.x, lane = tid & 31, w = tid >> 5;

    __shared__ unsigned sq[XQO_WOFF + 4096];

    // Stage even copy: sq[c*64 + wd] = XG[b][c][r] words (56 valid, 8 zero pad)
    for (int t = tid; t < 4096; t += 128) {
        int c = t >> 6, wd = t & 63;
        unsigned v = 0;
        if (wd < 56) v = XG[(size_t)(b * 64 + c) * 6272 + r * 56 + wd];
        sq[t] = v;
    }
    __syncthreads();
    // Odd-shifted copy: word = halves (2t+1, 2t+2)
    for (int t = tid; t < 4096; t += 128) {
        int c = t >> 6, wd = t & 63;
        unsigned lo = sq[(c << 6) + wd] >> 16;
        unsigned hi = (wd < 63) ? (sq[(c << 6) + wd + 1] << 16) : 0u;
        sq[XQO_WOFF + t] = lo | hi;
    }
    __syncthreads();

    // Per-lane B-fragment addressing
    int nj = lane >> 2;            // n within j-tile (0..7)
    int q0 = (lane & 3) << 1;      // 0,2,4,6
    int widx = (nj + q0) >> 1;
    const unsigned* bbase = sq + ((nj & 1) ? XQO_WOFF : 0) + widx + (w << 2);

    // Per-lane A-fragment addressing (z' words)
    const unsigned* zb = ZHW + (size_t)b * 64 * 128;
    int aoff = (lane >> 2) * 8 + (lane & 3);

    float acc[4][4];
#pragma unroll
    for (int u = 0; u < 4; ++u)
#pragma unroll
        for (int k = 0; k < 4; ++k) acc[u][k] = 0.0f;

    // Prologue: A-fragments for c = 0
    unsigned a0 = __ldg(zb + aoff);
    unsigned a1 = __ldg(zb + aoff + 64);
    unsigned a2 = __ldg(zb + aoff + 4);
    unsigned a3 = __ldg(zb + aoff + 68);

#pragma unroll 1
    for (int c = 0; c < 64; ++c) {
        // Prefetch next A-fragments before using current ones
        unsigned n0 = 0, n1 = 0, n2 = 0, n3 = 0;
        if (c < 63) {
            const unsigned* zn = zb + (c + 1) * 128 + aoff;
            n0 = __ldg(zn); n1 = __ldg(zn + 64);
            n2 = __ldg(zn + 4); n3 = __ldg(zn + 68);
        }
        const unsigned* bp = bbase + (c << 6);
#pragma unroll
        for (int u = 0; u < 4; ++u) {
            if (w + 4 * u < 13) {
                unsigned b0 = bp[u * 16];
                unsigned b1 = bp[u * 16 + 4];
                asm volatile(
                    "mma.sync.aligned.m16n8k16.row.col.f32.f16.f16.f32 "
                    "{%0,%1,%2,%3}, {%4,%5,%6,%7}, {%8,%9}, {%0,%1,%2,%3};"
                    : "+f"(acc[u][0]), "+f"(acc[u][1]), "+f"(acc[u][2]), "+f"(acc[u][3])
                    : "r"(a0), "r"(a1), "r"(a2), "r"(a3), "r"(b0), "r"(b1));
            }
        }
        a0 = n0; a1 = n1; a2 = n2; a3 = n3;
    }

    // Store H[b][r][p][j]
    int p0 = lane >> 2, jn = (lane & 3) << 1;
    float* Hb = Hbuf + (size_t)(b * 112 + r) * (16 * 112);
#pragma unroll
    for (int u = 0; u < 4; ++u) {
        int jt = w + 4 * u;
        if (jt < 13) {
            int j = jt * 8 + jn;
            *reinterpret_cast<float2*>(Hb + p0 * 112 + j)       = make_float2(acc[u][0], acc[u][1]);
            *reinterpret_cast<float2*>(Hb + (p0 + 8) * 112 + j) = make_float2(acc[u][2], acc[u][3]);
        }
    }
}

// ---- Kernel D: shift-add epilogue --------------------------------------------
__global__ __launch_bounds__(256) void epilogue(float* __restrict__ out) {
    int t = blockIdx.x * 256 + threadIdx.x;
    if (t >= 64 * 97 * 97) return;
    int b = t / 9409, rem = t - b * 9409;
    int i = rem / 97, j = rem - i * 97;
    const float* Hb = Hbuf + (size_t)b * (112 * 16 * 112);
    float s = 0.0f;
#pragma unroll
    for (int p = 0; p < 16; ++p)
        s += Hb[(size_t)((i + p) * 16 + p) * 112 + j];
    out[t] = s * 0.001f;
}

// ---- launch --------------------------------------------------------------------
extern "C" void kernel_launch(void* const* d_in, const int* in_sizes, int n_in,
                              void* d_out, int out_size) {
    const float* z  = (const float*)d_in[0];
    const float* x  = (const float*)d_in[1];
    const float* wz = (const float*)d_in[2];
    const float* bz = (const float*)d_in[3];
    const float* wx = (const float*)d_in[4];
    const float* bx = (const float*)d_in[5];
    float* out = (float*)d_out;

    prep_x<<<4096, 256>>>(x, wx, bx);
    prep_z<<<4096, 256>>>(z, wz, bz);
    corr<<<dim3(96, 64), 128>>>();
    epilogue<<<(64 * 97 * 97 + 255) / 256, 256>>>(out);
}